// round 3
// baseline (speedup 1.0000x reference)
#include <cuda_runtime.h>

// CapsuleLayer: B=32, I=32, C=2048, U=64, O=32, 3 routing iterations.
//
// Pipeline (all fp32):
//  k_gemm   : u_hat[b,c,u,o] = sum_i W[c,u,o,i] x[b,i,c]; fused s1 partials (c1 = 1/64 uniform)
//  k_squash : reduce s partials -> s, squash over O -> v   (writes g_v or d_out)
//  k_agree  : agree[c,u] = sum_{b,o} u_hat*v / B ; b += agree (or store on iter 1)
//  k_softmax: cnext[c,:] = softmax_u(b[c,:])
//  k_s      : s partials[g] = sum_{c in g} cnext[c,u]*u_hat[b,c,u,o]
// Sequence: gemm, squash(v1), agree, soft, s, squash(v2), agree, soft, s, squash(v3 -> out)

#define B_STRIDE 4194304   // C*U*O (per-batch stride in u_hat)
#define CH_STRIDE 2048     // U*O   (per-channel block)

__device__ float g_uhat[134217728];   // 512 MB scratch (B,C,U,O)
__device__ float g_sparts[16777216];  // 256 slots x 65536 (B,U,O) partials
__device__ float g_v[65536];          // v (B,U,O)
__device__ float g_b[131072];         // routing logits (C,U)
__device__ float g_cn[131072];        // softmax coupling coefficients (C,U)

#define FMA2(acc, a, b) asm("fma.rn.f32x2 %0, %1, %2, %0;" : "+l"(acc) : "l"(a), "l"(b))

// ---------------------------------------------------------------------------
// GEMM + fused s1 partial accumulation.
// grid (128 channel-groups of 16, 2 pair-halves), 256 threads, 64KB dyn smem.
// Thread owns (u,o) pairs; lane == o so u_hat stores are 128B-coalesced.
// Inner product paired over i: fma.rn.f32x2 accumulates (even-i, odd-i) sums.
// ---------------------------------------------------------------------------
__global__ __launch_bounds__(256, 2) void k_gemm(const float* __restrict__ x,
                                                 const float* __restrict__ w) {
    extern __shared__ float xs[];   // [16][32][32] : xs[cc][b][i], i contiguous
    const int tid = threadIdx.x;
    const int c0 = blockIdx.x * 16;

    // Stage x[b,i,c0..c0+15] into smem (coalesced over c)
    for (int idx = tid; idx < 16 * 1024; idx += 256) {
        int cc = idx & 15;
        int t = idx >> 4;
        int i = t & 31;
        int b = t >> 5;
        xs[(cc * 32 + b) * 32 + i] = x[(b * 32 + i) * 2048 + c0 + cc];
    }
    __syncthreads();

    for (int k = 0; k < 4; k++) {
        int p = blockIdx.y * 1024 + k * 256 + tid;   // pair index in [0,2048)
        int u = p >> 5, o = p & 31;
        int uo = u * 32 + o;

        float sacc[32];
#pragma unroll
        for (int b = 0; b < 32; b++) sacc[b] = 0.f;

        for (int cc = 0; cc < 16; cc++) {
            int c = c0 + cc;
            // W row: 32 contiguous floats = 16 natural (i,i+1) f32x2 pairs
            const ulonglong2* wrow =
                reinterpret_cast<const ulonglong2*>(w + (long)(c * 2048 + uo) * 32);
            unsigned long long wq[16];
#pragma unroll
            for (int q = 0; q < 8; q++) {
                ulonglong2 t = wrow[q];
                wq[2 * q] = t.x;
                wq[2 * q + 1] = t.y;
            }
            float* uhb = g_uhat + c * 2048 + uo;
            const float* xbase = &xs[cc * 1024];
#pragma unroll
            for (int b = 0; b < 32; b++) {
                unsigned long long acc = 0ull;   // (0.f, 0.f)
                const ulonglong2* xr =
                    reinterpret_cast<const ulonglong2*>(xbase + b * 32);
#pragma unroll
                for (int q = 0; q < 8; q++) {
                    ulonglong2 xv = xr[q];       // one LDS.128 -> two f32x2 operands
                    FMA2(acc, wq[2 * q], xv.x);
                    FMA2(acc, wq[2 * q + 1], xv.y);
                }
                float lo, hi;
                asm("mov.b64 {%0, %1}, %2;" : "=f"(lo), "=f"(hi) : "l"(acc));
                float val = lo + hi;
                uhb[b * B_STRIDE] = val;
                sacc[b] += val;
            }
        }
        // s1 partial for this channel-group (c1 = 1/64 uniform)
        float* sp = g_sparts + blockIdx.x * 65536 + uo;
#pragma unroll
        for (int b = 0; b < 32; b++) sp[b * 2048] = sacc[b] * 0.015625f;
    }
}

// ---------------------------------------------------------------------------
// Reduce s partials + squash over O. grid 256 x 256 threads.
// lane == o, each warp owns exactly one (b,u) row.
// ---------------------------------------------------------------------------
__global__ void k_squash(int nparts, float* __restrict__ out_ext, int use_ext) {
    int e = blockIdx.x * 256 + threadIdx.x;   // < 65536
    float a0 = 0.f, a1 = 0.f, a2 = 0.f, a3 = 0.f;
    for (int p = 0; p < nparts; p += 4) {
        a0 += g_sparts[(p + 0) * 65536 + e];
        a1 += g_sparts[(p + 1) * 65536 + e];
        a2 += g_sparts[(p + 2) * 65536 + e];
        a3 += g_sparts[(p + 3) * 65536 + e];
    }
    float s = (a0 + a1) + (a2 + a3);
    float sq = s * s;
#pragma unroll
    for (int off = 16; off > 0; off >>= 1)
        sq += __shfl_xor_sync(0xffffffffu, sq, off);
    float scale = sq / ((1.f + sq) * sqrtf(sq + 1e-8f));
    float res = s * scale;
    if (use_ext) out_ext[e] = res;
    else g_v[e] = res;
}

// ---------------------------------------------------------------------------
// agree[c,u] = (1/B) sum_{b,o} u_hat[b,c,u,o] * v[b,u,o];  b_logits update.
// grid 256 (8 channels each), 8 warps; warp owns u in {w, w+8, ...}, lane == o.
// v rows cached in registers once per u, reused across the 8 channels.
// ---------------------------------------------------------------------------
__global__ __launch_bounds__(256) void k_agree(int accumulate) {
    const int warp = threadIdx.x >> 5, lane = threadIdx.x & 31;
    const int c0 = blockIdx.x * 8;
    for (int u = warp; u < 64; u += 8) {
        float vreg[32];
#pragma unroll
        for (int b = 0; b < 32; b++) vreg[b] = g_v[b * 2048 + u * 32 + lane];
        float part[8];
#pragma unroll
        for (int cc = 0; cc < 8; cc++) part[cc] = 0.f;
#pragma unroll
        for (int b = 0; b < 32; b++) {
            const float* ub = g_uhat + b * B_STRIDE + c0 * CH_STRIDE + u * 32 + lane;
#pragma unroll
            for (int cc = 0; cc < 8; cc++)
                part[cc] += ub[cc * CH_STRIDE] * vreg[b];
        }
#pragma unroll
        for (int cc = 0; cc < 8; cc++) {
#pragma unroll
            for (int off = 16; off > 0; off >>= 1)
                part[cc] += __shfl_xor_sync(0xffffffffu, part[cc], off);
            if (lane == 0) {
                int idx = (c0 + cc) * 64 + u;
                float agree = part[cc] * 0.03125f;   // / B
                g_b[idx] = (accumulate ? g_b[idx] : 0.f) + agree;
            }
        }
    }
}

// softmax over U per channel. grid 256, warp per channel (2 values per lane).
__global__ void k_softmax() {
    int warp = threadIdx.x >> 5, lane = threadIdx.x & 31;
    int c = blockIdx.x * 8 + warp;
    float x0 = g_b[c * 64 + lane];
    float x1 = g_b[c * 64 + 32 + lane];
    float m = fmaxf(x0, x1);
#pragma unroll
    for (int off = 16; off > 0; off >>= 1)
        m = fmaxf(m, __shfl_xor_sync(0xffffffffu, m, off));
    float e0 = expf(x0 - m), e1 = expf(x1 - m);
    float sum = e0 + e1;
#pragma unroll
    for (int off = 16; off > 0; off >>= 1)
        sum += __shfl_xor_sync(0xffffffffu, sum, off);
    float inv = 1.f / sum;
    g_cn[c * 64 + lane] = e0 * inv;
    g_cn[c * 64 + 32 + lane] = e1 * inv;
}

// ---------------------------------------------------------------------------
// s partials: s_part[g][b,u,o] = sum_{cc<8} cnext[c0+cc,u] * u_hat[b,c0+cc,u,o]
// grid 256 (8 channels each), 8 warps; lane == o, warp owns 8 u's.
// ---------------------------------------------------------------------------
__global__ __launch_bounds__(256) void k_s() {
    const int tid = threadIdx.x;
    const int warp = tid >> 5, lane = tid & 31;
    const int c0 = blockIdx.x * 8;
    __shared__ float cn[8][64];
    for (int idx = tid; idx < 512; idx += 256)
        cn[idx >> 6][idx & 63] = g_cn[(c0 + (idx >> 6)) * 64 + (idx & 63)];
    __syncthreads();

    for (int u = warp; u < 64; u += 8) {
        float cw[8];
#pragma unroll
        for (int cc = 0; cc < 8; cc++) cw[cc] = cn[cc][u];
        float sacc[32];
#pragma unroll
        for (int b = 0; b < 32; b++) sacc[b] = 0.f;
#pragma unroll
        for (int b = 0; b < 32; b++) {
            const float* ub = g_uhat + b * B_STRIDE + c0 * CH_STRIDE + u * 32 + lane;
#pragma unroll
            for (int cc = 0; cc < 8; cc++)
                sacc[b] += cw[cc] * ub[cc * CH_STRIDE];
        }
        float* sp = g_sparts + blockIdx.x * 65536 + u * 32 + lane;
#pragma unroll
        for (int b = 0; b < 32; b++) sp[b * 2048] = sacc[b];
    }
}

// ---------------------------------------------------------------------------

extern "C" void kernel_launch(void* const* d_in, const int* in_sizes, int n_in,
                              void* d_out, int out_size) {
    const float* x = (const float*)d_in[0];
    const float* w = (const float*)d_in[1];
    // weight (134M elems) is the larger input; be robust to ordering
    if (in_sizes[0] > in_sizes[1]) { const float* t = x; x = w; w = t; }
    float* out = (float*)d_out;

    cudaFuncSetAttribute(k_gemm, cudaFuncAttributeMaxDynamicSharedMemorySize, 65536);

    dim3 gg(128, 2);
    k_gemm<<<gg, 256, 65536>>>(x, w);            // u_hat + s1 partials (128 slots)
    k_squash<<<256, 256>>>(128, out, 0);         // v1
    k_agree<<<256, 256>>>(0);                    // b2 = agree1
    k_softmax<<<256, 256>>>();                   // c2
    k_s<<<256, 256>>>();                         // s2 partials (256 slots)
    k_squash<<<256, 256>>>(256, out, 0);         // v2
    k_agree<<<256, 256>>>(1);                    // b3 = b2 + agree2
    k_softmax<<<256, 256>>>();                   // c3
    k_s<<<256, 256>>>();                         // s3 partials
    k_squash<<<256, 256>>>(256, out, 1);         // v3 -> output (agree3 is dead code)
}

// round 4
// speedup vs baseline: 1.5126x; 1.5126x over previous
#include <cuda_runtime.h>
#include <cstdint>

// CapsuleLayer: B=32, I=32, C=2048, U=64, O=32, 3 routing iterations.
//
// Pipeline:
//  k_gemm   : u_hat[c,b,u,o] = sum_i W[c,u,o,i] x[b,i,c]; fused s1 partials (c1 uniform 1/64)
//  k_squash : reduce s partials -> s, squash over O -> v
//  k_fused  : ONE pass over u_hat per routing step: agree (DRAM read) -> cluster-merge
//             b-halves via DSMEM -> logit update -> softmax -> s_{t+1} (L2 re-read),
//             s partials accumulated in registers across all channels of the cluster.
// Sequence: gemm, squash(v1), fused(b2,c2,s2), squash(v2), fused(b3,c3,s3), squash(v3->out)

#define FMA2(acc, a, b) asm("fma.rn.f32x2 %0, %1, %2, %0;" : "+l"(acc) : "l"(a), "l"(b))

__device__ float g_uhat[134217728];   // 512 MB scratch, layout (c,b,u,o): c*65536 + b*2048 + u*32 + o
__device__ float g_sparts[16777216];  // partial s buffers: slot*65536 + b*2048 + u*32 + o
__device__ float g_v[65536];          // v (B,U,O)
__device__ float g_b[131072];         // routing logits (C,U)

// ---------------------------------------------------------------------------
// GEMM + fused s1 partials. grid (128 ch-groups of 16, 2 uo-halves), 256 thr,
// 64KB smem. lane == o -> coalesced stores. f32x2 packed FMA over i-pairs.
// ---------------------------------------------------------------------------
__global__ __launch_bounds__(256, 2) void k_gemm(const float* __restrict__ x,
                                                 const float* __restrict__ w) {
    extern __shared__ float xs[];   // [16][32][32] : xs[cc][b][i]
    const int tid = threadIdx.x;
    const int c0 = blockIdx.x * 16;

    for (int idx = tid; idx < 16 * 1024; idx += 256) {
        int cc = idx & 15;
        int t = idx >> 4;
        int i = t & 31;
        int b = t >> 5;
        xs[(cc * 32 + b) * 32 + i] = x[(b * 32 + i) * 2048 + c0 + cc];
    }
    __syncthreads();

    for (int k = 0; k < 4; k++) {
        int p = blockIdx.y * 1024 + k * 256 + tid;   // (u,o) index in [0,2048)

        float sacc[32];
#pragma unroll
        for (int b = 0; b < 32; b++) sacc[b] = 0.f;

        for (int cc = 0; cc < 16; cc++) {
            int c = c0 + cc;
            const ulonglong2* wrow =
                reinterpret_cast<const ulonglong2*>(w + (long)(c * 2048 + p) * 32);
            unsigned long long wq[16];
#pragma unroll
            for (int q = 0; q < 8; q++) {
                ulonglong2 t = wrow[q];
                wq[2 * q] = t.x;
                wq[2 * q + 1] = t.y;
            }
            float* uhb = g_uhat + (long)c * 65536 + p;
            const float* xbase = &xs[cc * 1024];
#pragma unroll
            for (int b = 0; b < 32; b++) {
                unsigned long long acc = 0ull;
                const ulonglong2* xr =
                    reinterpret_cast<const ulonglong2*>(xbase + b * 32);
#pragma unroll
                for (int q = 0; q < 8; q++) {
                    ulonglong2 xv = xr[q];
                    FMA2(acc, wq[2 * q], xv.x);
                    FMA2(acc, wq[2 * q + 1], xv.y);
                }
                float lo, hi;
                asm("mov.b64 {%0, %1}, %2;" : "=f"(lo), "=f"(hi) : "l"(acc));
                float val = lo + hi;
                uhb[b * 2048] = val;
                sacc[b] += val;
            }
        }
        float* sp = g_sparts + blockIdx.x * 65536 + p;
#pragma unroll
        for (int b = 0; b < 32; b++) sp[b * 2048] = sacc[b] * 0.015625f;  // c1 = 1/64
    }
}

// ---------------------------------------------------------------------------
// Reduce nparts s-partials + squash over O. grid 256 x 256. lane == o.
// ---------------------------------------------------------------------------
__global__ void k_squash(int nparts, float* __restrict__ out_ext, int use_ext) {
    int e = blockIdx.x * 256 + threadIdx.x;
    float a0 = 0.f, a1 = 0.f, a2 = 0.f, a3 = 0.f;
    int p = 0;
    for (; p + 3 < nparts; p += 4) {
        a0 += g_sparts[(p + 0) * 65536 + e];
        a1 += g_sparts[(p + 1) * 65536 + e];
        a2 += g_sparts[(p + 2) * 65536 + e];
        a3 += g_sparts[(p + 3) * 65536 + e];
    }
    for (; p < nparts; p++) a0 += g_sparts[p * 65536 + e];
    float s = (a0 + a1) + (a2 + a3);
    float sq = s * s;
#pragma unroll
    for (int off = 16; off > 0; off >>= 1)
        sq += __shfl_xor_sync(0xffffffffu, sq, off);
    float scale = sq / ((1.f + sq) * sqrtf(sq + 1e-8f));
    float res = s * scale;
    if (use_ext) out_ext[e] = res;
    else g_v[e] = res;
}

// ---------------------------------------------------------------------------
// Fused routing step: agree -> logit update -> softmax -> s partials.
// 2-CTA cluster splits the batch (16 b each). grid 148 (74 clusters), 512 thr,
// 1 CTA/SM. Per channel: phase A streams the 128KB slice from DRAM computing
// agree (v from smem); halves merged via DSMEM store + cluster barrier; softmax
// computed redundantly per warp (shfl); phase C re-reads the slice (L2 hit)
// accumulating s into 64 register accumulators per thread. Partials at the end.
// Thread map: lane == o, warp w owns u in {w, w+16, w+32, w+48}, b = 16 local.
// ---------------------------------------------------------------------------
__global__ __launch_bounds__(512, 1) __cluster_dims__(2, 1, 1)
void k_fused(int add_prior, int store_b) {
    extern __shared__ float sm[];
    float* v_sm = sm;               // 32768 floats: this CTA's b-half of v
    float* agree_sm = sm + 32768;   // [2 parity][2 half][64 u]

    const int tid = threadIdx.x;
    const int w = tid >> 5;
    const int lane = tid & 31;
    const int r = blockIdx.x & 1;          // cluster rank (b-half)
    const int peer = r ^ 1;
    const int cid = blockIdx.x >> 1;
    const int nclus = gridDim.x >> 1;
    const int c_start = (cid * 2048) / nclus;
    const int c_end = ((cid + 1) * 2048) / nclus;

    for (int idx = tid; idx < 32768; idx += 512)
        v_sm[idx] = g_v[r * 32768 + idx];
    __syncthreads();

    float sacc[4][16];
#pragma unroll
    for (int j = 0; j < 4; j++)
#pragma unroll
        for (int bb = 0; bb < 16; bb++) sacc[j][bb] = 0.f;

    for (int c = c_start; c < c_end; c++) {
        const int par = c & 1;
        const float* uc = g_uhat + (long)c * 65536 + r * 16 * 2048 + lane;

        // Phase A: agree over this CTA's b-half
        float agg[4];
#pragma unroll
        for (int j = 0; j < 4; j++) {
            const int uoff = (w + 16 * j) * 32;
            const float* pu = uc + uoff;
            const float* pv = v_sm + uoff + lane;
            float a = 0.f;
#pragma unroll
            for (int bb = 0; bb < 16; bb++)
                a += __ldg(pu + bb * 2048) * pv[bb * 2048];
            agg[j] = a;
        }
#pragma unroll
        for (int j = 0; j < 4; j++)
            for (int off = 16; off > 0; off >>= 1)
                agg[j] += __shfl_xor_sync(0xffffffffu, agg[j], off);

        if (lane == 0) {
#pragma unroll
            for (int j = 0; j < 4; j++) {
                int u = w + 16 * j;
                float val = agg[j];
                agree_sm[(par * 2 + r) * 64 + u] = val;   // local copy
                unsigned int la = (unsigned int)__cvta_generic_to_shared(
                    &agree_sm[(par * 2 + r) * 64 + u]);
                asm volatile(
                    "{.reg .b32 ra; mapa.shared::cluster.u32 ra, %0, %1;"
                    " st.shared::cluster.f32 [ra], %2;}"
                    :: "r"(la), "r"(peer), "f"(val));
            }
        }
        asm volatile("barrier.cluster.arrive.aligned;" ::: "memory");
        asm volatile("barrier.cluster.wait.aligned;" ::: "memory");

        // Merge halves, update logits, softmax over 64 u (redundant per warp)
        float a0 = (agree_sm[(par * 2) * 64 + lane] +
                    agree_sm[(par * 2 + 1) * 64 + lane]) * 0.03125f;       // /B
        float a1 = (agree_sm[(par * 2) * 64 + 32 + lane] +
                    agree_sm[(par * 2 + 1) * 64 + 32 + lane]) * 0.03125f;
        if (add_prior) {
            a0 += g_b[c * 64 + lane];
            a1 += g_b[c * 64 + 32 + lane];
        }
        if (store_b && r == 0 && w == 0) {
            g_b[c * 64 + lane] = a0;
            g_b[c * 64 + 32 + lane] = a1;
        }
        float m = fmaxf(a0, a1);
        for (int off = 16; off > 0; off >>= 1)
            m = fmaxf(m, __shfl_xor_sync(0xffffffffu, m, off));
        float e0 = expf(a0 - m), e1 = expf(a1 - m);
        float sume = e0 + e1;
        for (int off = 16; off > 0; off >>= 1)
            sume += __shfl_xor_sync(0xffffffffu, sume, off);
        float inv = 1.f / sume;
        float c0v = e0 * inv, c1v = e1 * inv;
        float cn[4];
        cn[0] = __shfl_sync(0xffffffffu, c0v, w);
        cn[1] = __shfl_sync(0xffffffffu, c0v, w + 16);
        cn[2] = __shfl_sync(0xffffffffu, c1v, w);
        cn[3] = __shfl_sync(0xffffffffu, c1v, w + 16);

        // Phase C: s accumulation, re-read from L2
#pragma unroll
        for (int j = 0; j < 4; j++) {
            const float* pu = uc + (w + 16 * j) * 32;
            const float cj = cn[j];
#pragma unroll
            for (int bb = 0; bb < 16; bb++)
                sacc[j][bb] += cj * __ldg(pu + bb * 2048);
        }
    }

    // Write per-cluster s partials (this CTA's b-half slice)
    float* sp = g_sparts + cid * 65536 + (r * 16) * 2048 + lane;
#pragma unroll
    for (int j = 0; j < 4; j++)
#pragma unroll
        for (int bb = 0; bb < 16; bb++)
            sp[bb * 2048 + (w + 16 * j) * 32] = sacc[j][bb];
}

// ---------------------------------------------------------------------------

extern "C" void kernel_launch(void* const* d_in, const int* in_sizes, int n_in,
                              void* d_out, int out_size) {
    const float* x = (const float*)d_in[0];
    const float* w = (const float*)d_in[1];
    if (in_sizes[0] > in_sizes[1]) { const float* t = x; x = w; w = t; }
    float* out = (float*)d_out;

    cudaFuncSetAttribute(k_gemm, cudaFuncAttributeMaxDynamicSharedMemorySize, 65536);
    cudaFuncSetAttribute(k_fused, cudaFuncAttributeMaxDynamicSharedMemorySize, 132096);

    dim3 gg(128, 2);
    k_gemm<<<gg, 256, 65536>>>(x, w);          // u_hat + s1 partials (128 slots)
    k_squash<<<256, 256>>>(128, out, 0);       // v1 -> g_v
    k_fused<<<148, 512, 132096>>>(0, 1);       // agree1 -> b2 (stored) -> c2 -> s2 partials
    k_squash<<<256, 256>>>(74, out, 0);        // v2 -> g_v
    k_fused<<<148, 512, 132096>>>(1, 0);       // agree2 -> b3 -> c3 -> s3 partials
    k_squash<<<256, 256>>>(74, out, 1);        // v3 -> output (agree3 is dead code)
}

// round 5
// speedup vs baseline: 1.6986x; 1.1230x over previous
#include <cuda_runtime.h>
#include <cuda_fp16.h>
#include <cstdint>

// CapsuleLayer: B=32, I=32, C=2048, U=64, O=32, 3 routing iterations.
//
// u_hat scratch is fp16 (halves all LTS/DRAM traffic on the dominant tensor);
// all arithmetic/accumulation fp32.
//
//  k_gemm   : u_hat[c,b,u,o](fp16) = sum_i W[c,u,o,i] x[b,i,c]; fused s1 partials
//  k_squash : reduce s partials -> s, squash over O -> v
//  k_fused  : per routing step, one DRAM pass + one L2 pass over u_hat:
//             agree -> cluster DSMEM merge -> logits -> softmax -> s partials (regs)

#define FMA2(acc, a, b) asm("fma.rn.f32x2 %0, %1, %2, %0;" : "+l"(acc) : "l"(a), "l"(b))

__device__ __half g_uhat[134217728];  // 256 MB scratch (c,b,u,o): c*65536 + b*2048 + u*32 + o
__device__ float g_sparts[16777216];  // partial s: slot*65536 + b*2048 + u*32 + o
__device__ float g_v[65536];          // v (B,U,O)
__device__ float g_b[131072];         // routing logits (C,U)

// ---------------------------------------------------------------------------
// GEMM + fused s1 partials. grid (128 ch-groups of 16, 2 uo-halves), 256 thr.
// fp32 accumulate via packed f32x2 FMA over i-pairs; fp16 store.
// ---------------------------------------------------------------------------
__global__ __launch_bounds__(256, 2) void k_gemm(const float* __restrict__ x,
                                                 const float* __restrict__ w) {
    extern __shared__ float xs[];   // [16][32][32] : xs[cc][b][i]
    const int tid = threadIdx.x;
    const int c0 = blockIdx.x * 16;

    for (int idx = tid; idx < 16 * 1024; idx += 256) {
        int cc = idx & 15;
        int t = idx >> 4;
        int i = t & 31;
        int b = t >> 5;
        xs[(cc * 32 + b) * 32 + i] = x[(b * 32 + i) * 2048 + c0 + cc];
    }
    __syncthreads();

    for (int k = 0; k < 4; k++) {
        int p = blockIdx.y * 1024 + k * 256 + tid;   // (u,o) index in [0,2048)

        float sacc[32];
#pragma unroll
        for (int b = 0; b < 32; b++) sacc[b] = 0.f;

        for (int cc = 0; cc < 16; cc++) {
            int c = c0 + cc;
            const ulonglong2* wrow =
                reinterpret_cast<const ulonglong2*>(w + (long)(c * 2048 + p) * 32);
            unsigned long long wq[16];
#pragma unroll
            for (int q = 0; q < 8; q++) {
                ulonglong2 t = wrow[q];
                wq[2 * q] = t.x;
                wq[2 * q + 1] = t.y;
            }
            __half* uhb = g_uhat + (long)c * 65536 + p;
            const float* xbase = &xs[cc * 1024];
#pragma unroll
            for (int b = 0; b < 32; b++) {
                unsigned long long acc = 0ull;
                const ulonglong2* xr =
                    reinterpret_cast<const ulonglong2*>(xbase + b * 32);
#pragma unroll
                for (int q = 0; q < 8; q++) {
                    ulonglong2 xv = xr[q];
                    FMA2(acc, wq[2 * q], xv.x);
                    FMA2(acc, wq[2 * q + 1], xv.y);
                }
                float lo, hi;
                asm("mov.b64 {%0, %1}, %2;" : "=f"(lo), "=f"(hi) : "l"(acc));
                float val = lo + hi;
                uhb[b * 2048] = __float2half_rn(val);
                sacc[b] += val;
            }
        }
        float* sp = g_sparts + blockIdx.x * 65536 + p;
#pragma unroll
        for (int b = 0; b < 32; b++) sp[b * 2048] = sacc[b] * 0.015625f;  // c1 = 1/64
    }
}

// ---------------------------------------------------------------------------
// Reduce nparts s-partials + squash over O. grid 256 x 256. lane == o.
// ---------------------------------------------------------------------------
__global__ void k_squash(int nparts, float* __restrict__ out_ext, int use_ext) {
    int e = blockIdx.x * 256 + threadIdx.x;
    float a0 = 0.f, a1 = 0.f, a2 = 0.f, a3 = 0.f;
    int p = 0;
    for (; p + 3 < nparts; p += 4) {
        a0 += g_sparts[(p + 0) * 65536 + e];
        a1 += g_sparts[(p + 1) * 65536 + e];
        a2 += g_sparts[(p + 2) * 65536 + e];
        a3 += g_sparts[(p + 3) * 65536 + e];
    }
    for (; p < nparts; p++) a0 += g_sparts[p * 65536 + e];
    float s = (a0 + a1) + (a2 + a3);
    float sq = s * s;
#pragma unroll
    for (int off = 16; off > 0; off >>= 1)
        sq += __shfl_xor_sync(0xffffffffu, sq, off);
    float scale = sq / ((1.f + sq) * sqrtf(sq + 1e-8f));
    float res = s * scale;
    if (use_ext) out_ext[e] = res;
    else g_v[e] = res;
}

// ---------------------------------------------------------------------------
// Fused routing step. 2-CTA cluster splits batch (16 b each). grid 148, 512thr.
// Thread map: warp w in [0,16); lane = us*16 + op (us in {0,1}, op in [0,16)).
// Thread owns u = j*32 + w*2 + us (j in {0,1}) and o-pair {2op, 2op+1}:
// __half2 loads are fully 128B-coalesced per warp.
// Phase A: agree (DRAM read, v from smem) -> 16-lane segmented reduce ->
// DSMEM merge -> logits -> softmax -> Phase C: s accum from L2 re-read.
// ---------------------------------------------------------------------------
__global__ __launch_bounds__(512, 1) __cluster_dims__(2, 1, 1)
void k_fused(int add_prior, int store_b) {
    extern __shared__ float sm[];
    float* v_sm = sm;               // 32768 floats: this CTA's b-half of v
    float* agree_sm = sm + 32768;   // [2 parity][2 half][64 u]

    const int tid = threadIdx.x;
    const int w = tid >> 5;
    const int lane = tid & 31;
    const int us = lane >> 4;
    const int op = lane & 15;
    const int r = blockIdx.x & 1;          // cluster rank (b-half)
    const int peer = r ^ 1;
    const int cid = blockIdx.x >> 1;
    const int nclus = gridDim.x >> 1;
    const int c_start = (cid * 2048) / nclus;
    const int c_end = ((cid + 1) * 2048) / nclus;
    const int u0 = w * 2 + us;             // base u (j adds 32)

    for (int idx = tid; idx < 32768; idx += 512)
        v_sm[idx] = g_v[r * 32768 + idx];
    __syncthreads();

    float2 sacc[2][16];
#pragma unroll
    for (int j = 0; j < 2; j++)
#pragma unroll
        for (int bb = 0; bb < 16; bb++) sacc[j][bb] = make_float2(0.f, 0.f);

    for (int c = c_start; c < c_end; c++) {
        const int par = c & 1;
        const __half* uc =
            g_uhat + (long)c * 65536 + (r * 16) * 2048 + u0 * 32 + 2 * op;

        // Phase A: agree over this CTA's b-half (fp16 u_hat, fp32 math)
        float agg[2];
#pragma unroll
        for (int j = 0; j < 2; j++) {
            const __half* pu = uc + j * 1024;          // u += 32
            const float* pv = v_sm + (j * 32 + u0) * 32 + 2 * op;
            float a = 0.f;
#pragma unroll
            for (int bb = 0; bb < 16; bb++) {
                float2 f = __half22float2(
                    __ldg(reinterpret_cast<const __half2*>(pu + bb * 2048)));
                float2 vv = *reinterpret_cast<const float2*>(pv + bb * 2048);
                a += f.x * vv.x + f.y * vv.y;
            }
            agg[j] = a;
        }
        // segmented reduce over the 16 op-lanes of each us half
#pragma unroll
        for (int j = 0; j < 2; j++)
#pragma unroll
            for (int off = 8; off > 0; off >>= 1)
                agg[j] += __shfl_xor_sync(0xffffffffu, agg[j], off);

        if (op == 0) {
#pragma unroll
            for (int j = 0; j < 2; j++) {
                int u = j * 32 + u0;
                float val = agg[j];
                agree_sm[(par * 2 + r) * 64 + u] = val;
                unsigned int la = (unsigned int)__cvta_generic_to_shared(
                    &agree_sm[(par * 2 + r) * 64 + u]);
                asm volatile(
                    "{.reg .b32 ra; mapa.shared::cluster.u32 ra, %0, %1;"
                    " st.shared::cluster.f32 [ra], %2;}"
                    :: "r"(la), "r"(peer), "f"(val));
            }
        }
        asm volatile("barrier.cluster.arrive.aligned;" ::: "memory");
        asm volatile("barrier.cluster.wait.aligned;" ::: "memory");

        // Merge halves, update logits, softmax over 64 u (redundant per warp)
        float a0 = (agree_sm[(par * 2) * 64 + lane] +
                    agree_sm[(par * 2 + 1) * 64 + lane]) * 0.03125f;   // /B
        float a1 = (agree_sm[(par * 2) * 64 + 32 + lane] +
                    agree_sm[(par * 2 + 1) * 64 + 32 + lane]) * 0.03125f;
        if (add_prior) {
            a0 += g_b[c * 64 + lane];
            a1 += g_b[c * 64 + 32 + lane];
        }
        if (store_b && r == 0 && w == 0) {
            g_b[c * 64 + lane] = a0;
            g_b[c * 64 + 32 + lane] = a1;
        }
        float m = fmaxf(a0, a1);
        for (int off = 16; off > 0; off >>= 1)
            m = fmaxf(m, __shfl_xor_sync(0xffffffffu, m, off));
        float e0 = expf(a0 - m), e1 = expf(a1 - m);
        float sume = e0 + e1;
        for (int off = 16; off > 0; off >>= 1)
            sume += __shfl_xor_sync(0xffffffffu, sume, off);
        float inv = 1.f / sume;
        float c0v = e0 * inv;   // c for u = lane
        float c1v = e1 * inv;   // c for u = 32 + lane
        float cn[2];
        cn[0] = __shfl_sync(0xffffffffu, c0v, u0);
        cn[1] = __shfl_sync(0xffffffffu, c1v, u0);

        // Phase C: s accumulation, re-read from L2
#pragma unroll
        for (int j = 0; j < 2; j++) {
            const __half* pu = uc + j * 1024;
            const float cj = cn[j];
#pragma unroll
            for (int bb = 0; bb < 16; bb++) {
                float2 f = __half22float2(
                    __ldg(reinterpret_cast<const __half2*>(pu + bb * 2048)));
                sacc[j][bb].x += cj * f.x;
                sacc[j][bb].y += cj * f.y;
            }
        }
    }

    // Write per-cluster s partials (this CTA's b-half slice)
    float* sp = g_sparts + cid * 65536 + (r * 16) * 2048 + u0 * 32 + 2 * op;
#pragma unroll
    for (int j = 0; j < 2; j++)
#pragma unroll
        for (int bb = 0; bb < 16; bb++)
            *reinterpret_cast<float2*>(sp + j * 1024 + bb * 2048) = sacc[j][bb];
}

// ---------------------------------------------------------------------------

extern "C" void kernel_launch(void* const* d_in, const int* in_sizes, int n_in,
                              void* d_out, int out_size) {
    const float* x = (const float*)d_in[0];
    const float* w = (const float*)d_in[1];
    if (in_sizes[0] > in_sizes[1]) { const float* t = x; x = w; w = t; }
    float* out = (float*)d_out;

    cudaFuncSetAttribute(k_gemm, cudaFuncAttributeMaxDynamicSharedMemorySize, 65536);
    cudaFuncSetAttribute(k_fused, cudaFuncAttributeMaxDynamicSharedMemorySize, 132096);

    dim3 gg(128, 2);
    k_gemm<<<gg, 256, 65536>>>(x, w);          // u_hat(fp16) + s1 partials (128 slots)
    k_squash<<<256, 256>>>(128, out, 0);       // v1 -> g_v
    k_fused<<<148, 512, 132096>>>(0, 1);       // agree1 -> b2 -> c2 -> s2 partials
    k_squash<<<256, 256>>>(74, out, 0);        // v2 -> g_v
    k_fused<<<148, 512, 132096>>>(1, 0);       // agree2 -> b3 -> c3 -> s3 partials
    k_squash<<<256, 256>>>(74, out, 1);        // v3 -> output (agree3 dead)
}

// round 6
// speedup vs baseline: 1.8163x; 1.0693x over previous
#include <cuda_runtime.h>
#include <cuda_fp16.h>
#include <cstdint>

// CapsuleLayer: B=32, I=32, C=2048, U=64, O=32, 3 routing iterations.
// u_hat scratch fp16; all math fp32.
//  k_gemm   : u_hat[c,b,u,o] = sum_i W[c,u,o,i] x[b,i,c]; W staged via swizzled
//             smem (coalesced LDG, conflict-free LDS); fused s1 partials.
//  k_squash : reduce s partials -> s, squash over O -> v.
//  k_fused  : one DRAM pass per routing step; u_hat slice held in REGISTERS
//             across agree -> DSMEM cluster merge -> softmax -> s accumulation.
// 5 leading nop launches align ncu's "-s 5 -c 1" onto k_gemm.

#define FMA2(acc, a, b) asm("fma.rn.f32x2 %0, %1, %2, %0;" : "+l"(acc) : "l"(a), "l"(b))

__device__ __half g_uhat[134217728];  // 256 MB (c,b,u,o): c*65536 + b*2048 + u*32 + o
__device__ float g_sparts[16777216];  // partial s: slot*65536 + b*2048 + u*32 + o
__device__ float g_v[65536];          // v (B,U,O)
__device__ float g_b[131072];         // routing logits (C,U)

__global__ void k_nop() {}

// ---------------------------------------------------------------------------
// GEMM + fused s1 partials. grid (128 ch-groups of 16, 2 uo-halves), 256 thr.
// Per (k,cc): warp cooperatively loads its W[c, p0:p0+32, 0:32] 4KB tile into
// a per-warp smem slab with XOR-of-row swizzle (stores AND reads conflict-free),
// then each lane pulls its row into registers and runs the f32x2 b-loop.
// ---------------------------------------------------------------------------
__global__ __launch_bounds__(256, 2) void k_gemm(const float* __restrict__ x,
                                                 const float* __restrict__ w) {
    extern __shared__ float xs[];        // [0,16384): x tiles; then 8 warp slabs
    float* wsm = xs + 16384;             // 8 x 1024 floats
    const int tid = threadIdx.x;
    const int warp = tid >> 5, lane = tid & 31;
    const int c0 = blockIdx.x * 16;

    for (int idx = tid; idx < 16 * 1024; idx += 256) {
        int cc = idx & 15;
        int t = idx >> 4;
        int i = t & 31;
        int b = t >> 5;
        xs[(cc * 32 + b) * 32 + i] = x[(b * 32 + i) * 2048 + c0 + cc];
    }
    __syncthreads();

    ulonglong2* wslab = reinterpret_cast<ulonglong2*>(wsm + warp * 1024);

    for (int k = 0; k < 4; k++) {
        const int p0 = blockIdx.y * 1024 + k * 256 + warp * 32;
        const int p = p0 + lane;

        float sacc[32];
#pragma unroll
        for (int b = 0; b < 32; b++) sacc[b] = 0.f;

        for (int cc = 0; cc < 16; cc++) {
            const int c = c0 + cc;
            // Cooperative, coalesced load of the warp's 4KB W tile (swizzled)
            const ulonglong2* wg =
                reinterpret_cast<const ulonglong2*>(w + ((long)c * 2048 + p0) * 32);
#pragma unroll
            for (int it = 0; it < 8; it++) {
                int chunk = it * 32 + lane;            // 16B unit, 256 total
                ulonglong2 val = wg[chunk];            // 512B/warp, coalesced
                int row = chunk >> 3, q = chunk & 7;
                wslab[row * 8 + (q ^ (row & 7))] = val;
            }
            __syncwarp();
            unsigned long long wq[16];
#pragma unroll
            for (int q = 0; q < 8; q++) {
                ulonglong2 t = wslab[lane * 8 + (q ^ (lane & 7))];  // conflict-free
                wq[2 * q] = t.x;
                wq[2 * q + 1] = t.y;
            }
            __syncwarp();

            __half* uhb = g_uhat + (long)c * 65536 + p;
            const float* xbase = &xs[cc * 1024];
#pragma unroll
            for (int b = 0; b < 32; b++) {
                unsigned long long acc = 0ull;
                const ulonglong2* xr =
                    reinterpret_cast<const ulonglong2*>(xbase + b * 32);
#pragma unroll
                for (int q = 0; q < 8; q++) {
                    ulonglong2 xv = xr[q];             // smem broadcast
                    FMA2(acc, wq[2 * q], xv.x);
                    FMA2(acc, wq[2 * q + 1], xv.y);
                }
                float lo, hi;
                asm("mov.b64 {%0, %1}, %2;" : "=f"(lo), "=f"(hi) : "l"(acc));
                float val = lo + hi;
                uhb[b * 2048] = __float2half_rn(val);
                sacc[b] += val;
            }
        }
        float* sp = g_sparts + blockIdx.x * 65536 + p;
#pragma unroll
        for (int b = 0; b < 32; b++) sp[b * 2048] = sacc[b] * 0.015625f;  // c1=1/64
    }
}

// ---------------------------------------------------------------------------
// Reduce nparts s-partials + squash over O. grid 256 x 256. lane == o.
// ---------------------------------------------------------------------------
__global__ void k_squash(int nparts, float* __restrict__ out_ext, int use_ext) {
    int e = blockIdx.x * 256 + threadIdx.x;
    float a0 = 0.f, a1 = 0.f, a2 = 0.f, a3 = 0.f;
    int p = 0;
    for (; p + 3 < nparts; p += 4) {
        a0 += g_sparts[(p + 0) * 65536 + e];
        a1 += g_sparts[(p + 1) * 65536 + e];
        a2 += g_sparts[(p + 2) * 65536 + e];
        a3 += g_sparts[(p + 3) * 65536 + e];
    }
    for (; p < nparts; p++) a0 += g_sparts[p * 65536 + e];
    float s = (a0 + a1) + (a2 + a3);
    float sq = s * s;
#pragma unroll
    for (int off = 16; off > 0; off >>= 1)
        sq += __shfl_xor_sync(0xffffffffu, sq, off);
    float scale = sq / ((1.f + sq) * sqrtf(sq + 1e-8f));
    float res = s * scale;
    if (use_ext) out_ext[e] = res;
    else g_v[e] = res;
}

// ---------------------------------------------------------------------------
// Fused routing step. 2-CTA cluster splits batch (16 b each). grid 148, 512thr.
// lane = us*16+op; thread owns u = j*32 + w*2 + us, o-pair {2op,2op+1}.
// Phase A loads the u_hat slice ONCE (coalesced half2, held in registers),
// computes agree; DSMEM merge + softmax; phase C is register-only FMA.
// ---------------------------------------------------------------------------
__global__ __launch_bounds__(512, 1) __cluster_dims__(2, 1, 1)
void k_fused(int add_prior, int store_b) {
    extern __shared__ float sm[];
    float* v_sm = sm;               // 32768 floats: this CTA's b-half of v
    float* agree_sm = sm + 32768;   // [2 parity][2 half][64 u]

    const int tid = threadIdx.x;
    const int w = tid >> 5;
    const int lane = tid & 31;
    const int us = lane >> 4;
    const int op = lane & 15;
    const int r = blockIdx.x & 1;
    const int peer = r ^ 1;
    const int cid = blockIdx.x >> 1;
    const int nclus = gridDim.x >> 1;
    const int c_start = (cid * 2048) / nclus;
    const int c_end = ((cid + 1) * 2048) / nclus;
    const int u0 = w * 2 + us;

    for (int idx = tid; idx < 32768; idx += 512)
        v_sm[idx] = g_v[r * 32768 + idx];
    __syncthreads();

    float2 sacc[2][16];
#pragma unroll
    for (int j = 0; j < 2; j++)
#pragma unroll
        for (int bb = 0; bb < 16; bb++) sacc[j][bb] = make_float2(0.f, 0.f);

    for (int c = c_start; c < c_end; c++) {
        const int par = c & 1;
        const __half* uc =
            g_uhat + (long)c * 65536 + (r * 16) * 2048 + u0 * 32 + 2 * op;

        // Phase A: load slice into registers, compute agree
        __half2 uh[2][16];
        float agg[2];
#pragma unroll
        for (int j = 0; j < 2; j++) {
            const __half* pu = uc + j * 1024;
            const float* pv = v_sm + (j * 32 + u0) * 32 + 2 * op;
            float a = 0.f;
#pragma unroll
            for (int bb = 0; bb < 16; bb++) {
                __half2 h = __ldg(reinterpret_cast<const __half2*>(pu + bb * 2048));
                uh[j][bb] = h;
                float2 f = __half22float2(h);
                float2 vv = *reinterpret_cast<const float2*>(pv + bb * 2048);
                a += f.x * vv.x + f.y * vv.y;
            }
            agg[j] = a;
        }
#pragma unroll
        for (int j = 0; j < 2; j++)
#pragma unroll
            for (int off = 8; off > 0; off >>= 1)
                agg[j] += __shfl_xor_sync(0xffffffffu, agg[j], off);

        if (op == 0) {
#pragma unroll
            for (int j = 0; j < 2; j++) {
                int u = j * 32 + u0;
                float val = agg[j];
                agree_sm[(par * 2 + r) * 64 + u] = val;
                unsigned int la = (unsigned int)__cvta_generic_to_shared(
                    &agree_sm[(par * 2 + r) * 64 + u]);
                asm volatile(
                    "{.reg .b32 ra; mapa.shared::cluster.u32 ra, %0, %1;"
                    " st.shared::cluster.f32 [ra], %2;}"
                    :: "r"(la), "r"(peer), "f"(val));
            }
        }
        asm volatile("barrier.cluster.arrive.aligned;" ::: "memory");
        asm volatile("barrier.cluster.wait.aligned;" ::: "memory");

        // Merge halves, logits, softmax over 64 u (redundant per warp)
        float a0 = (agree_sm[(par * 2) * 64 + lane] +
                    agree_sm[(par * 2 + 1) * 64 + lane]) * 0.03125f;
        float a1 = (agree_sm[(par * 2) * 64 + 32 + lane] +
                    agree_sm[(par * 2 + 1) * 64 + 32 + lane]) * 0.03125f;
        if (add_prior) {
            a0 += g_b[c * 64 + lane];
            a1 += g_b[c * 64 + 32 + lane];
        }
        if (store_b && r == 0 && w == 0) {
            g_b[c * 64 + lane] = a0;
            g_b[c * 64 + 32 + lane] = a1;
        }
        float m = fmaxf(a0, a1);
        for (int off = 16; off > 0; off >>= 1)
            m = fmaxf(m, __shfl_xor_sync(0xffffffffu, m, off));
        float e0 = expf(a0 - m), e1 = expf(a1 - m);
        float sume = e0 + e1;
        for (int off = 16; off > 0; off >>= 1)
            sume += __shfl_xor_sync(0xffffffffu, sume, off);
        float inv = 1.f / sume;
        float c0v = e0 * inv;
        float c1v = e1 * inv;
        float cn[2];
        cn[0] = __shfl_sync(0xffffffffu, c0v, u0);
        cn[1] = __shfl_sync(0xffffffffu, c1v, u0);

        // Phase C: register-only s accumulation
#pragma unroll
        for (int j = 0; j < 2; j++) {
            const float cj = cn[j];
#pragma unroll
            for (int bb = 0; bb < 16; bb++) {
                float2 f = __half22float2(uh[j][bb]);
                sacc[j][bb].x += cj * f.x;
                sacc[j][bb].y += cj * f.y;
            }
        }
    }

    float* sp = g_sparts + cid * 65536 + (r * 16) * 2048 + u0 * 32 + 2 * op;
#pragma unroll
    for (int j = 0; j < 2; j++)
#pragma unroll
        for (int bb = 0; bb < 16; bb++)
            *reinterpret_cast<float2*>(sp + j * 1024 + bb * 2048) = sacc[j][bb];
}

// ---------------------------------------------------------------------------

extern "C" void kernel_launch(void* const* d_in, const int* in_sizes, int n_in,
                              void* d_out, int out_size) {
    const float* x = (const float*)d_in[0];
    const float* w = (const float*)d_in[1];
    if (in_sizes[0] > in_sizes[1]) { const float* t = x; x = w; w = t; }
    float* out = (float*)d_out;

    cudaFuncSetAttribute(k_gemm, cudaFuncAttributeMaxDynamicSharedMemorySize, 98304);
    cudaFuncSetAttribute(k_fused, cudaFuncAttributeMaxDynamicSharedMemorySize, 132096);

    // 5 nops so ncu's fixed "-s 5 -c 1" profiles k_gemm (launch #6)
    for (int i = 0; i < 5; i++) k_nop<<<1, 32>>>();

    dim3 gg(128, 2);
    k_gemm<<<gg, 256, 98304>>>(x, w);          // u_hat(fp16) + s1 partials (128 slots)
    k_squash<<<256, 256>>>(128, out, 0);       // v1 -> g_v
    k_fused<<<148, 512, 132096>>>(0, 1);       // agree1 -> b2 -> c2 -> s2 partials
    k_squash<<<256, 256>>>(74, out, 0);        // v2 -> g_v
    k_fused<<<148, 512, 132096>>>(1, 0);       // agree2 -> b3 -> c3 -> s3 partials
    k_squash<<<256, 256>>>(74, out, 1);        // v3 -> output (agree3 dead)
}

// round 8
// speedup vs baseline: 2.5996x; 1.4313x over previous
#include <cuda_runtime.h>
#include <cuda_fp16.h>
#include <cstdint>

// CapsuleLayer: B=32, I=32, C=2048, U=64, O=32, 3 routing iterations.
//  k_gemm_mma : fp16 mma.sync.m16n8k16 (legacy tensor path; tcgen05 not available
//               at this ptxas target). Per channel: D[b=32, p=2048] = x_c · W_c^T.
//               A = x (fp16 smem, frags cached in regs per channel); B = W streamed
//               LDG.128 -> cvt f16x2 -> double-buffered smem; logical-k permutation
//               makes each B-frag one LDS.64. Epilogue: smem transpose -> coalesced
//               fp16 u_hat stores; s1 partials fused in registers.
//  k_squash   : reduce s partials -> squash over O -> v.
//  k_fused    : one DRAM pass per routing step (agree -> DSMEM merge -> softmax ->
//               register s accumulation), unchanged from R6.

__device__ __half g_uhat[134217728];  // 256 MB (c,b,u,o): c*65536 + b*2048 + uo
__device__ float g_sparts[16777216];  // 256 slots x 65536 (b*2048 + uo)
__device__ float g_v[65536];
__device__ float g_b[131072];

__global__ void k_nop() {}

// smem (bytes): x_h 16KB | W_h 2x16KB | epi 32 x 528B
#define SM_XH 0
#define SM_WH 16384
#define SM_EPI 49152
#define SM_TOT 66048

__device__ __forceinline__ void mma16816(float d[4], uint32_t a0, uint32_t a1,
                                         uint32_t a2, uint32_t a3,
                                         uint32_t b0, uint32_t b1) {
    asm volatile(
        "mma.sync.aligned.m16n8k16.row.col.f32.f16.f16.f32 "
        "{%0,%1,%2,%3}, {%4,%5,%6,%7}, {%8,%9}, {%0,%1,%2,%3};"
        : "+f"(d[0]), "+f"(d[1]), "+f"(d[2]), "+f"(d[3])
        : "r"(a0), "r"(a1), "r"(a2), "r"(a3), "r"(b0), "r"(b1));
}

__global__ __launch_bounds__(256) void k_gemm_mma(const float* __restrict__ x,
                                                  const float* __restrict__ wt) {
    extern __shared__ char smem[];
    __half* x_h = reinterpret_cast<__half*>(smem + SM_XH);
    const int tid = threadIdx.x;
    const int warp = tid >> 5, lane = tid & 31;
    const int r = lane >> 2, q = lane & 3;   // mma group row / quad id
    const int c0 = blockIdx.x * 8;

    // Stage x -> fp16 smem: x_h[cc][b][i] (i contiguous)
    for (int idx = tid; idx < 8192; idx += 256) {
        int cc = idx & 7, bi = idx >> 3;
        x_h[cc * 1024 + bi] = __float2half_rn(x[bi * 2048 + c0 + cc]);
    }

    // W tile prefetch (tile n = chunk*8+cc: rows chunk*256..+255 of channel c0+cc)
    float4 pre[8];
    const float4* wbase4 = reinterpret_cast<const float4*>(wt);
    {
        const float4* s4 = wbase4 + (long)c0 * 16384;   // tile 0
#pragma unroll
        for (int j = 0; j < 8; j++) pre[j] = s4[j * 256 + tid];
    }

    __syncthreads();   // x_h ready

    // cvt + store prefetched W tile into swizzled fp16 buffer
    const int uu = tid & 7;    // fixed 8B-unit per thread
    auto sts_w = [&](int buf) {
        char* base = smem + SM_WH + buf * 16384;
#pragma unroll
        for (int j = 0; j < 8; j++) {
            int p = j * 32 + (tid >> 3);
            int up = uu ^ ((p & 2) << 1);        // bank swizzle (2-cycle floor)
            __half2 h0 = __floats2half2_rn(pre[j].x, pre[j].y);
            __half2 h1 = __floats2half2_rn(pre[j].z, pre[j].w);
            uint2 val;
            val.x = *reinterpret_cast<uint32_t*>(&h0);
            val.y = *reinterpret_cast<uint32_t*>(&h1);
            *reinterpret_cast<uint2*>(base + p * 64 + up * 8) = val;
        }
    };
    sts_w(0);
    __syncthreads();

    float sacc[4][2][4];

    for (int n = 0; n < 64; n++) {
        const int cc = n & 7, chunk = n >> 3;
        const int c = c0 + cc;

        if (cc == 0) {
#pragma unroll
            for (int nt = 0; nt < 4; nt++)
#pragma unroll
                for (int bt = 0; bt < 2; bt++)
#pragma unroll
                    for (int jj = 0; jj < 4; jj++) sacc[nt][bt][jj] = 0.f;
        }

        // Prefetch next W tile into registers (consumed after the mma section)
        if (n < 63) {
            const int n1 = n + 1;
            const float4* s4 =
                wbase4 + (long)(c0 + (n1 & 7)) * 16384 + (long)(n1 >> 3) * 2048;
#pragma unroll
            for (int j = 0; j < 8; j++) pre[j] = s4[j * 256 + tid];
        }

        // A fragments for this channel: a[bt][ks][4]
        // logical k 2q,2q+1 <-> phys i 4q,4q+1 ; k 2q+8,2q+9 <-> i 4q+2,4q+3
        uint32_t A[2][2][4];
#pragma unroll
        for (int bt = 0; bt < 2; bt++)
#pragma unroll
            for (int ks = 0; ks < 2; ks++) {
                uint2 v1 = *reinterpret_cast<const uint2*>(
                    &x_h[cc * 1024 + (bt * 16 + r) * 32 + ks * 16 + q * 4]);
                uint2 v2 = *reinterpret_cast<const uint2*>(
                    &x_h[cc * 1024 + (bt * 16 + r + 8) * 32 + ks * 16 + q * 4]);
                A[bt][ks][0] = v1.x;
                A[bt][ks][1] = v2.x;
                A[bt][ks][2] = v1.y;
                A[bt][ks][3] = v2.y;
            }

        // MMA: 4 N-tiles x 2 b-tiles x 2 k-steps
        float d[4][2][4];
#pragma unroll
        for (int nt = 0; nt < 4; nt++)
#pragma unroll
            for (int bt = 0; bt < 2; bt++)
#pragma unroll
                for (int jj = 0; jj < 4; jj++) d[nt][bt][jj] = 0.f;

        char* wb = smem + SM_WH + (n & 1) * 16384;
#pragma unroll
        for (int nt = 0; nt < 4; nt++) {
            const int p = warp * 32 + nt * 8 + r;
            const int xm = (p & 2) << 1;
#pragma unroll
            for (int ks = 0; ks < 2; ks++) {
                uint2 bf = *reinterpret_cast<const uint2*>(
                    wb + p * 64 + ((ks * 4 + q) ^ xm) * 8);
                mma16816(d[nt][0], A[0][ks][0], A[0][ks][1], A[0][ks][2], A[0][ks][3],
                         bf.x, bf.y);
                mma16816(d[nt][1], A[1][ks][0], A[1][ks][1], A[1][ks][2], A[1][ks][3],
                         bf.x, bf.y);
            }
        }

        // Epilogue: s1 accumulate + fp16 transpose via epi smem
#pragma unroll
        for (int nt = 0; nt < 4; nt++)
#pragma unroll
            for (int bt = 0; bt < 2; bt++) {
#pragma unroll
                for (int jj = 0; jj < 4; jj++) sacc[nt][bt][jj] += d[nt][bt][jj];
                int col = warp * 32 + nt * 8 + 2 * q;
                int row = bt * 16 + r;
                __half2 lo = __floats2half2_rn(d[nt][bt][0], d[nt][bt][1]);
                __half2 hi = __floats2half2_rn(d[nt][bt][2], d[nt][bt][3]);
                *reinterpret_cast<__half2*>(smem + SM_EPI + row * 528 + col * 2) = lo;
                *reinterpret_cast<__half2*>(smem + SM_EPI + (row + 8) * 528 + col * 2) = hi;
            }
        __syncthreads();

        // Coalesced u_hat store: thread -> (b = tid/8, 64B segment = tid%8)
        {
            int b = tid >> 3, seg = tid & 7;
            const uint4* src =
                reinterpret_cast<const uint4*>(smem + SM_EPI + b * 528 + seg * 64);
            uint4* dst = reinterpret_cast<uint4*>(
                g_uhat + (long)c * 65536 + b * 2048 + chunk * 256 + seg * 32);
#pragma unroll
            for (int t4 = 0; t4 < 4; t4++) dst[t4] = src[t4];
        }

        if (n < 63) sts_w((n + 1) & 1);
        __syncthreads();

        if (cc == 7) {   // s1 partials for this chunk (c1 = 1/64)
            float* sp = g_sparts + blockIdx.x * 65536 + chunk * 256;
#pragma unroll
            for (int nt = 0; nt < 4; nt++)
#pragma unroll
                for (int bt = 0; bt < 2; bt++) {
                    int col = warp * 32 + nt * 8 + 2 * q;
                    int row = bt * 16 + r;
                    float2 v0 = make_float2(sacc[nt][bt][0] * 0.015625f,
                                            sacc[nt][bt][1] * 0.015625f);
                    float2 v1 = make_float2(sacc[nt][bt][2] * 0.015625f,
                                            sacc[nt][bt][3] * 0.015625f);
                    *reinterpret_cast<float2*>(sp + row * 2048 + col) = v0;
                    *reinterpret_cast<float2*>(sp + (row + 8) * 2048 + col) = v1;
                }
        }
    }
}

// ---------------------------------------------------------------------------
__global__ void k_squash(int nparts, float* __restrict__ out_ext, int use_ext) {
    int e = blockIdx.x * 256 + threadIdx.x;
    float a0 = 0.f, a1 = 0.f, a2 = 0.f, a3 = 0.f;
    int p = 0;
    for (; p + 3 < nparts; p += 4) {
        a0 += g_sparts[(p + 0) * 65536 + e];
        a1 += g_sparts[(p + 1) * 65536 + e];
        a2 += g_sparts[(p + 2) * 65536 + e];
        a3 += g_sparts[(p + 3) * 65536 + e];
    }
    for (; p < nparts; p++) a0 += g_sparts[p * 65536 + e];
    float s = (a0 + a1) + (a2 + a3);
    float sq = s * s;
#pragma unroll
    for (int off = 16; off > 0; off >>= 1)
        sq += __shfl_xor_sync(0xffffffffu, sq, off);
    float scale = sq / ((1.f + sq) * sqrtf(sq + 1e-8f));
    float res = s * scale;
    if (use_ext) out_ext[e] = res;
    else g_v[e] = res;
}

// ---------------------------------------------------------------------------
__global__ __launch_bounds__(512, 1) __cluster_dims__(2, 1, 1)
void k_fused(int add_prior, int store_b) {
    extern __shared__ float sm[];
    float* v_sm = sm;
    float* agree_sm = sm + 32768;

    const int tid = threadIdx.x;
    const int w = tid >> 5;
    const int lane = tid & 31;
    const int us = lane >> 4;
    const int op = lane & 15;
    const int r = blockIdx.x & 1;
    const int peer = r ^ 1;
    const int cid = blockIdx.x >> 1;
    const int nclus = gridDim.x >> 1;
    const int c_start = (cid * 2048) / nclus;
    const int c_end = ((cid + 1) * 2048) / nclus;
    const int u0 = w * 2 + us;

    for (int idx = tid; idx < 32768; idx += 512)
        v_sm[idx] = g_v[r * 32768 + idx];
    __syncthreads();

    float2 sacc[2][16];
#pragma unroll
    for (int j = 0; j < 2; j++)
#pragma unroll
        for (int bb = 0; bb < 16; bb++) sacc[j][bb] = make_float2(0.f, 0.f);

    for (int c = c_start; c < c_end; c++) {
        const int par = c & 1;
        const __half* uc =
            g_uhat + (long)c * 65536 + (r * 16) * 2048 + u0 * 32 + 2 * op;

        __half2 uh[2][16];
        float agg[2];
#pragma unroll
        for (int j = 0; j < 2; j++) {
            const __half* pu = uc + j * 1024;
            const float* pv = v_sm + (j * 32 + u0) * 32 + 2 * op;
            float a = 0.f;
#pragma unroll
            for (int bb = 0; bb < 16; bb++) {
                __half2 h = __ldg(reinterpret_cast<const __half2*>(pu + bb * 2048));
                uh[j][bb] = h;
                float2 f = __half22float2(h);
                float2 vv = *reinterpret_cast<const float2*>(pv + bb * 2048);
                a += f.x * vv.x + f.y * vv.y;
            }
            agg[j] = a;
        }
#pragma unroll
        for (int j = 0; j < 2; j++)
#pragma unroll
            for (int off = 8; off > 0; off >>= 1)
                agg[j] += __shfl_xor_sync(0xffffffffu, agg[j], off);

        if (op == 0) {
#pragma unroll
            for (int j = 0; j < 2; j++) {
                int u = j * 32 + u0;
                float val = agg[j];
                agree_sm[(par * 2 + r) * 64 + u] = val;
                unsigned int la = (unsigned int)__cvta_generic_to_shared(
                    &agree_sm[(par * 2 + r) * 64 + u]);
                asm volatile(
                    "{.reg .b32 ra; mapa.shared::cluster.u32 ra, %0, %1;"
                    " st.shared::cluster.f32 [ra], %2;}"
                    :: "r"(la), "r"(peer), "f"(val));
            }
        }
        asm volatile("barrier.cluster.arrive.aligned;" ::: "memory");
        asm volatile("barrier.cluster.wait.aligned;" ::: "memory");

        float a0 = (agree_sm[(par * 2) * 64 + lane] +
                    agree_sm[(par * 2 + 1) * 64 + lane]) * 0.03125f;
        float a1 = (agree_sm[(par * 2) * 64 + 32 + lane] +
                    agree_sm[(par * 2 + 1) * 64 + 32 + lane]) * 0.03125f;
        if (add_prior) {
            a0 += g_b[c * 64 + lane];
            a1 += g_b[c * 64 + 32 + lane];
        }
        if (store_b && r == 0 && w == 0) {
            g_b[c * 64 + lane] = a0;
            g_b[c * 64 + 32 + lane] = a1;
        }
        float m = fmaxf(a0, a1);
        for (int off = 16; off > 0; off >>= 1)
            m = fmaxf(m, __shfl_xor_sync(0xffffffffu, m, off));
        float e0 = expf(a0 - m), e1 = expf(a1 - m);
        float sume = e0 + e1;
        for (int off = 16; off > 0; off >>= 1)
            sume += __shfl_xor_sync(0xffffffffu, sume, off);
        float inv = 1.f / sume;
        float c0v = e0 * inv;
        float c1v = e1 * inv;
        float cn[2];
        cn[0] = __shfl_sync(0xffffffffu, c0v, u0);
        cn[1] = __shfl_sync(0xffffffffu, c1v, u0);

#pragma unroll
        for (int j = 0; j < 2; j++) {
            const float cj = cn[j];
#pragma unroll
            for (int bb = 0; bb < 16; bb++) {
                float2 f = __half22float2(uh[j][bb]);
                sacc[j][bb].x += cj * f.x;
                sacc[j][bb].y += cj * f.y;
            }
        }
    }

    float* sp = g_sparts + cid * 65536 + (r * 16) * 2048 + u0 * 32 + 2 * op;
#pragma unroll
    for (int j = 0; j < 2; j++)
#pragma unroll
        for (int bb = 0; bb < 16; bb++)
            *reinterpret_cast<float2*>(sp + j * 1024 + bb * 2048) = sacc[j][bb];
}

// ---------------------------------------------------------------------------

extern "C" void kernel_launch(void* const* d_in, const int* in_sizes, int n_in,
                              void* d_out, int out_size) {
    const float* x = (const float*)d_in[0];
    const float* w = (const float*)d_in[1];
    if (in_sizes[0] > in_sizes[1]) { const float* t = x; x = w; w = t; }
    float* out = (float*)d_out;

    cudaFuncSetAttribute(k_gemm_mma, cudaFuncAttributeMaxDynamicSharedMemorySize, SM_TOT);
    cudaFuncSetAttribute(k_fused, cudaFuncAttributeMaxDynamicSharedMemorySize, 132096);

    k_nop<<<1, 32>>>();                        // #1 (profiler alignment)
    k_gemm_mma<<<256, 256, SM_TOT>>>(x, w);    // #2: u_hat(fp16) + s1 partials
    k_squash<<<256, 256>>>(256, out, 0);       // #3: v1
    k_fused<<<148, 512, 132096>>>(0, 1);       // #4: agree1 -> b2 -> c2 -> s2
    k_squash<<<256, 256>>>(74, out, 0);        // #5: v2
    k_fused<<<148, 512, 132096>>>(1, 0);       // #6: agree2 -> b3 -> c3 -> s3 (ncu target)
    k_squash<<<256, 256>>>(74, out, 1);        // #7: v3 -> output
}